// round 5
// baseline (speedup 1.0000x reference)
#include <cuda_runtime.h>

#define TIMES 4

// Persistent grid-stride kernel: exactly one wave of blocks, each looping over
// its share of float4 lanes. Eliminates wave-transition drain/fill (~13 waves
// before). Per iteration: 4 independent streaming loads (MLP=4), dependent
// accumulate/reset chain, 4 streaming stores. Single-touch both ways ->
// __ldcs/__stcs keep the streams out of L2 retention.
__global__ __launch_bounds__(256) void spike_kernel_p(
    const float4* __restrict__ in, float4* __restrict__ out, int n_per_chunk /* float4 count */)
{
    int stride = gridDim.x * blockDim.x;
    for (int i = blockIdx.x * blockDim.x + threadIdx.x; i < n_per_chunk; i += stride) {
        float4 I0 = __ldcs(&in[(size_t)0 * n_per_chunk + i]);
        float4 I1 = __ldcs(&in[(size_t)1 * n_per_chunk + i]);
        float4 I2 = __ldcs(&in[(size_t)2 * n_per_chunk + i]);
        float4 I3 = __ldcs(&in[(size_t)3 * n_per_chunk + i]);

        float4 V = make_float4(0.f, 0.f, 0.f, 0.f);

        #define STEP(I)                                                  \
            V.x += (I).x; V.y += (I).y; V.z += (I).z; V.w += (I).w;      \
            V.x = (fabsf(V.x) > 1.0f) ? 0.0f : V.x;                      \
            V.y = (fabsf(V.y) > 1.0f) ? 0.0f : V.y;                      \
            V.z = (fabsf(V.z) > 1.0f) ? 0.0f : V.z;                      \
            V.w = (fabsf(V.w) > 1.0f) ? 0.0f : V.w;

        STEP(I0); __stcs(&out[(size_t)0 * n_per_chunk + i], V);
        STEP(I1); __stcs(&out[(size_t)1 * n_per_chunk + i], V);
        STEP(I2); __stcs(&out[(size_t)2 * n_per_chunk + i], V);
        STEP(I3); __stcs(&out[(size_t)3 * n_per_chunk + i], V);

        #undef STEP
    }
}

extern "C" void kernel_launch(void* const* d_in, const int* in_sizes, int n_in,
                              void* d_out, int out_size) {
    const float4* in = (const float4*)d_in[0];
    float4* out = (float4*)d_out;
    int n_per_chunk = out_size / TIMES / 4;  // float4 elements per chunk (4,194,304)

    // One full wave: 8 blocks/SM (256 thr, 32 regs -> 2048 thr/SM) x SM count.
    int dev = 0, sms = 148;
    cudaGetDevice(&dev);
    cudaDeviceGetAttribute(&sms, cudaDevAttrMultiProcessorCount, dev);
    int threads = 256;
    int blocks = sms * 8;
    int max_blocks = (n_per_chunk + threads - 1) / threads;
    if (blocks > max_blocks) blocks = max_blocks;
    spike_kernel_p<<<blocks, threads>>>(in, out, n_per_chunk);
}

// round 6
// speedup vs baseline: 1.1568x; 1.1568x over previous
#include <cuda_runtime.h>

#define TIMES 4

// One float4 (16B) per thread per time-step, eager full grid (no persistence —
// R5 showed grid-stride loops regress: block oversubscription hides wave
// transitions better than loop-carried streaming). 4 independent front-batched
// streaming loads (MLP=4, saturates the LTS cap), dependent accumulate/reset
// chain, streaming stores. __ldcs/__stcs: single-touch streams, no L2 retention.
__global__ __launch_bounds__(512) void spike_kernel(
    const float4* __restrict__ in, float4* __restrict__ out, int n_per_chunk /* float4 count */)
{
    int i = blockIdx.x * blockDim.x + threadIdx.x;
    if (i >= n_per_chunk) return;

    float4 I0 = __ldcs(&in[(size_t)0 * n_per_chunk + i]);
    float4 I1 = __ldcs(&in[(size_t)1 * n_per_chunk + i]);
    float4 I2 = __ldcs(&in[(size_t)2 * n_per_chunk + i]);
    float4 I3 = __ldcs(&in[(size_t)3 * n_per_chunk + i]);

    float4 V = make_float4(0.f, 0.f, 0.f, 0.f);

    #define STEP(I)                                                  \
        V.x += (I).x; V.y += (I).y; V.z += (I).z; V.w += (I).w;      \
        V.x = (fabsf(V.x) > 1.0f) ? 0.0f : V.x;                      \
        V.y = (fabsf(V.y) > 1.0f) ? 0.0f : V.y;                      \
        V.z = (fabsf(V.z) > 1.0f) ? 0.0f : V.z;                      \
        V.w = (fabsf(V.w) > 1.0f) ? 0.0f : V.w;

    STEP(I0); __stcs(&out[(size_t)0 * n_per_chunk + i], V);
    STEP(I1); __stcs(&out[(size_t)1 * n_per_chunk + i], V);
    STEP(I2); __stcs(&out[(size_t)2 * n_per_chunk + i], V);
    STEP(I3); __stcs(&out[(size_t)3 * n_per_chunk + i], V);

    #undef STEP
}

extern "C" void kernel_launch(void* const* d_in, const int* in_sizes, int n_in,
                              void* d_out, int out_size) {
    const float4* in = (const float4*)d_in[0];
    float4* out = (float4*)d_out;
    int n_per_chunk = out_size / TIMES / 4;  // float4 elements per chunk (4,194,304)
    int threads = 512;
    int blocks = (n_per_chunk + threads - 1) / threads;
    spike_kernel<<<blocks, threads>>>(in, out, n_per_chunk);
}